// round 3
// baseline (speedup 1.0000x reference)
#include <cuda_runtime.h>
#include <cuda_fp16.h>

#define TEXN   1024
#define TT     (TEXN * TEXN)
#define CH     16
#define BB     4
#define HH     768
#define WW     768
#define HW     (HH * WW)
#define NPIX   (BB * HW)

#define CLAMP_LO (-123.68f)
#define CLAMP_HI (151.061f)

// Channel-interleaved clamped texture in fp16: [y][x][c], c fastest (33.5 MB,
// L2-resident). +32 halves of zero padding: the paired-row 64B load at
// x0 == T-1 reads up to 32B past the last texel; pad is never written, stays
// zero (bilinear weight there is exactly 0, 0*0 = 0, no NaN).
__device__ __half g_tex[TT * CH + 32];

// ---------------------------------------------------------------------------
// Pass 1: clamp + transpose + fp16 convert, [C,T,T] f32 -> [T,T,C] f16.
// __ldcs on input: stream it through L2 evict-first so the g_tex writes stay
// resident for the sampler.
// ---------------------------------------------------------------------------
__global__ __launch_bounds__(256)
void clamp_transpose_kernel(const float* __restrict__ data) {
    int p4 = (blockIdx.x * blockDim.x + threadIdx.x) * 4;
    if (p4 >= TT) return;

    __half h[4][CH];
#pragma unroll
    for (int c = 0; c < CH; c++) {
        float4 t = __ldcs(reinterpret_cast<const float4*>(&data[c * TT + p4]));
        h[0][c] = __float2half_rn(fminf(fmaxf(t.x, CLAMP_LO), CLAMP_HI));
        h[1][c] = __float2half_rn(fminf(fmaxf(t.y, CLAMP_LO), CLAMP_HI));
        h[2][c] = __float2half_rn(fminf(fmaxf(t.z, CLAMP_LO), CLAMP_HI));
        h[3][c] = __float2half_rn(fminf(fmaxf(t.w, CLAMP_LO), CLAMP_HI));
    }

    uint4* dst = reinterpret_cast<uint4*>(g_tex + (size_t)p4 * CH);
#pragma unroll
    for (int i = 0; i < 4; i++) {
        const uint4* src = reinterpret_cast<const uint4*>(&h[i][0]);
        dst[i * 2 + 0] = src[0];
        dst[i * 2 + 1] = src[1];
    }
}

// ---------------------------------------------------------------------------
// Pass 2: bilinear sample. 4 threads/pixel, 64 pixels/block (256 threads).
//   Loads:  lane q loads 16B quarter of the 64B (x0,x1) row span, for rows
//           y0 and y1 (2 LDG.128/thread). shfl_xor(2) exchanges x0<->x1
//           halves so every lane holds both x-corners for its 8 channels.
//   Stores: results staged in smem [16 ch][64 px], written back as 256B
//           contiguous float4 streams per channel (__stcs).
// ---------------------------------------------------------------------------
__device__ __forceinline__ void unpack8(uint4 u, float* f) {
    float2 a = __half22float2(*reinterpret_cast<__half2*>(&u.x));
    float2 b = __half22float2(*reinterpret_cast<__half2*>(&u.y));
    float2 c = __half22float2(*reinterpret_cast<__half2*>(&u.z));
    float2 d = __half22float2(*reinterpret_cast<__half2*>(&u.w));
    f[0] = a.x; f[1] = a.y; f[2] = b.x; f[3] = b.y;
    f[4] = c.x; f[5] = c.y; f[6] = d.x; f[7] = d.y;
}

__device__ __forceinline__ uint4 shfl_xor2(uint4 u) {
    uint4 v;
    v.x = __shfl_xor_sync(0xffffffffu, u.x, 2);
    v.y = __shfl_xor_sync(0xffffffffu, u.y, 2);
    v.z = __shfl_xor_sync(0xffffffffu, u.z, 2);
    v.w = __shfl_xor_sync(0xffffffffu, u.w, 2);
    return v;
}

#define SOUT_STRIDE 68   // 16B-aligned rows (LDS.128 legal), staggers banks

__global__ __launch_bounds__(256)
void sample_kernel(const float2* __restrict__ grid, float* __restrict__ out) {
    __shared__ __align__(16) float s_out[CH * SOUT_STRIDE];

    int tid = threadIdx.x;
    int lp  = tid >> 2;                       // local pixel 0..63
    int q   = tid & 3;
    int pix = blockIdx.x * 64 + lp;           // grid sized exactly: no guard

    float2 g = __ldg(&grid[pix]);

    float ix = (g.x + 1.0f) * 0.5f * (float)(TEXN - 1);
    float iy = (g.y + 1.0f) * 0.5f * (float)(TEXN - 1);
    ix = fminf(fmaxf(ix, 0.0f), (float)(TEXN - 1));
    iy = fminf(fmaxf(iy, 0.0f), (float)(TEXN - 1));

    float x0f = floorf(ix);
    float y0f = floorf(iy);
    float wx = ix - x0f;
    float wy = iy - y0f;

    int x0 = (int)x0f;
    int y0 = (int)y0f;
    int y1 = min(y0 + 1, TEXN - 1);

    // 64B row span covering texels (y, x0) and (y, x0+1); lane q takes 16B.
    const __half* base0 = g_tex + ((size_t)(y0 * TEXN + x0)) * CH + q * 8;
    const __half* base1 = g_tex + ((size_t)(y1 * TEXN + x0)) * CH + q * 8;
    uint4 u0 = *reinterpret_cast<const uint4*>(base0);
    uint4 u1 = *reinterpret_cast<const uint4*>(base1);

    // Partner lane (q^2) holds the other x-texel's same channel half.
    uint4 v0 = shfl_xor2(u0);
    uint4 v1 = shfl_xor2(u1);

    bool isX0 = (q & 2) == 0;     // my data is x0's if q<2, else x1's
    uint4 a0 = isX0 ? u0 : v0;    // x0, row y0
    uint4 b0 = isX0 ? v0 : u0;    // x1, row y0
    uint4 a1 = isX0 ? u1 : v1;    // x0, row y1
    uint4 b1 = isX0 ? v1 : u1;    // x1, row y1

    float fa0[8], fb0[8], fa1[8], fb1[8];
    unpack8(a0, fa0);
    unpack8(b0, fb0);
    unpack8(a1, fa1);
    unpack8(b1, fb1);

    // r[j] = bilinear result for channel ch_lo + j
    float r[8];
#pragma unroll
    for (int j = 0; j < 8; j++) {
        float r0 = fa0[j] + (fb0[j] - fa0[j]) * wx;
        float r1 = fa1[j] + (fb1[j] - fa1[j]) * wx;
        r[j] = r0 + (r1 - r0) * wy;
    }

    // Lanes q and q^2 computed identical channels; split the store 4/4.
    int ch_lo = (q & 1) * 8;
    int sub   = (q >> 1) * 4;
#pragma unroll
    for (int j = 0; j < 4; j++) {
        s_out[(ch_lo + sub + j) * SOUT_STRIDE + lp] = r[sub + j];
    }

    __syncthreads();

    // Writeback: thread i -> channel i>>4, float4 #(i&15). 256B contiguous
    // per channel, streaming stores.
    int c = tid >> 4;
    int v = tid & 15;
    float4 val = *reinterpret_cast<const float4*>(&s_out[c * SOUT_STRIDE + v * 4]);

    int pix_base = blockIdx.x * 64;
    int b  = pix_base / HW;
    int hw = pix_base - b * HW;   // multiple of 64
    float* o = out + ((size_t)b * CH + c) * HW + hw + v * 4;
    __stcs(reinterpret_cast<float4*>(o), val);
}

extern "C" void kernel_launch(void* const* d_in, const int* in_sizes, int n_in,
                              void* d_out, int out_size) {
    const float* x_grid = (const float*)d_in[0];
    const float* data   = (const float*)d_in[1];
    if (n_in >= 2 && in_sizes[0] == TT * CH) {
        data   = (const float*)d_in[0];
        x_grid = (const float*)d_in[1];
    }

    float* out = (float*)d_out;

    {
        int threads = 256;
        int blocks = (TT / 4 + threads - 1) / threads;  // 1024
        clamp_transpose_kernel<<<blocks, threads>>>(data);
    }
    {
        int blocks = NPIX / 64;                          // 36864, exact
        sample_kernel<<<blocks, 256>>>((const float2*)x_grid, out);
    }
}

// round 5
// speedup vs baseline: 1.1051x; 1.1051x over previous
#include <cuda_runtime.h>
#include <cuda_fp16.h>

#define TEXN   1024
#define TT     (TEXN * TEXN)
#define CH     16
#define BB     4
#define HH     768
#define WW     768
#define HW     (HH * WW)
#define NPIX   (BB * HW)

#define CLAMP_LO (-123.68f)
#define CLAMP_HI (151.061f)

// Channel-interleaved clamped texture in fp16: [y][x][c], c fastest (33.5 MB,
// L2-resident). +32 halves zero padding: the 64B (x0,x1) span load at
// x0 == T-1 reads 32B past the last texel; wx==0 there so the pad (never
// written, zero-initialized) contributes 0*0 — no NaN.
__device__ __half g_tex[TT * CH + 32];

// ---------------------------------------------------------------------------
// Pass 1: clamp + transpose + fp16 convert, [C,T,T] f32 -> [T,T,C] f16.
// ---------------------------------------------------------------------------
__global__ __launch_bounds__(256)
void clamp_transpose_kernel(const float* __restrict__ data) {
    int p4 = (blockIdx.x * blockDim.x + threadIdx.x) * 4;
    if (p4 >= TT) return;

    __half h[4][CH];
#pragma unroll
    for (int c = 0; c < CH; c++) {
        float4 t = __ldcs(reinterpret_cast<const float4*>(&data[c * TT + p4]));
        h[0][c] = __float2half_rn(fminf(fmaxf(t.x, CLAMP_LO), CLAMP_HI));
        h[1][c] = __float2half_rn(fminf(fmaxf(t.y, CLAMP_LO), CLAMP_HI));
        h[2][c] = __float2half_rn(fminf(fmaxf(t.z, CLAMP_LO), CLAMP_HI));
        h[3][c] = __float2half_rn(fminf(fmaxf(t.w, CLAMP_LO), CLAMP_HI));
    }

    uint4* dst = reinterpret_cast<uint4*>(g_tex + (size_t)p4 * CH);
#pragma unroll
    for (int i = 0; i < 4; i++) {
        const uint4* src = reinterpret_cast<const uint4*>(&h[i][0]);
        dst[i * 2 + 0] = src[0];
        dst[i * 2 + 1] = src[1];
    }
}

// ---------------------------------------------------------------------------
// Pass 2: bilinear sample. 4 threads/pixel, 64 px/block (256 threads).
//   Loads: lane q loads the q-th 16B quarter of the 64B (x0,x1) row span,
//          for rows y0,y1 (2 LDG.128). Lanes of a pixel hit the same 1-2
//          128B lines -> ~2.5 L1 wavefronts/px.
//   Exchange: minimum 8B/row via 2 SHFL.32 — each lane gets the OTHER
//          x-corner's values for ITS OWN 4 channels. No duplicate compute:
//          lane q owns channels {0-3, 8-11, 4-7, 12-15}[q].
//   Stores: staged in smem [16ch][64px], written back as 256B-contiguous
//          float4 streams (__stcs).
// ---------------------------------------------------------------------------
#define SOUT_STRIDE 68   // floats; 16B-aligned rows for LDS.128

__global__ __launch_bounds__(256)
void sample_kernel(const float2* __restrict__ grid, float* __restrict__ out) {
    __shared__ __align__(16) float s_out[CH * SOUT_STRIDE];

    int tid = threadIdx.x;
    int lp  = tid >> 2;                 // local pixel 0..63
    int q   = tid & 3;
    int pix = blockIdx.x * 64 + lp;     // exact grid: no guard

    float2 g = __ldg(&grid[pix]);

    float ix = (g.x + 1.0f) * 0.5f * (float)(TEXN - 1);
    float iy = (g.y + 1.0f) * 0.5f * (float)(TEXN - 1);
    ix = fminf(fmaxf(ix, 0.0f), (float)(TEXN - 1));
    iy = fminf(fmaxf(iy, 0.0f), (float)(TEXN - 1));

    float x0f = floorf(ix);
    float y0f = floorf(iy);
    float wx = ix - x0f;
    float wy = iy - y0f;

    int x0 = (int)x0f;
    int y0 = (int)y0f;
    int y1 = min(y0 + 1, TEXN - 1);

    bool hiX = (q & 2) != 0;            // lanes q2,q3 hold x1 data

    // 64B span = [x0 ch0-7 | x0 ch8-15 | x1 ch0-7 | x1 ch8-15]; lane q -> 16B.
    const __half* b0 = g_tex + ((size_t)(y0 * TEXN + x0)) * CH + q * 8;
    const __half* b1 = g_tex + ((size_t)(y1 * TEXN + x0)) * CH + q * 8;
    uint4 u0 = *reinterpret_cast<const uint4*>(b0);
    uint4 u1 = *reinterpret_cast<const uint4*>(b1);

    // Minimal exchange: send the half my partner's channels need, receive the
    // other-x values for MY 4 channels. 2 SHFL per row.
    unsigned recv0a = __shfl_xor_sync(0xffffffffu, hiX ? u0.x : u0.z, 2);
    unsigned recv0b = __shfl_xor_sync(0xffffffffu, hiX ? u0.y : u0.w, 2);
    unsigned recv1a = __shfl_xor_sync(0xffffffffu, hiX ? u1.x : u1.z, 2);
    unsigned recv1b = __shfl_xor_sync(0xffffffffu, hiX ? u1.y : u1.w, 2);

    unsigned own0a = hiX ? u0.z : u0.x;
    unsigned own0b = hiX ? u0.w : u0.y;
    unsigned own1a = hiX ? u1.z : u1.x;
    unsigned own1b = hiX ? u1.w : u1.y;

    // own = my-x value for my channels; recv = other-x. One weight select
    // gives correct lerp orientation for both lane roles.
    float w_own = hiX ? wx : (1.0f - wx);
    float w_oth = 1.0f - w_own;

    float2 oa0 = __half22float2(*reinterpret_cast<__half2*>(&own0a));
    float2 ob0 = __half22float2(*reinterpret_cast<__half2*>(&own0b));
    float2 ra0 = __half22float2(*reinterpret_cast<__half2*>(&recv0a));
    float2 rb0 = __half22float2(*reinterpret_cast<__half2*>(&recv0b));
    float2 oa1 = __half22float2(*reinterpret_cast<__half2*>(&own1a));
    float2 ob1 = __half22float2(*reinterpret_cast<__half2*>(&own1b));
    float2 ra1 = __half22float2(*reinterpret_cast<__half2*>(&recv1a));
    float2 rb1 = __half22float2(*reinterpret_cast<__half2*>(&recv1b));

    float r0[4], r1[4], res[4];
    r0[0] = oa0.x * w_own + ra0.x * w_oth;
    r0[1] = oa0.y * w_own + ra0.y * w_oth;
    r0[2] = ob0.x * w_own + rb0.x * w_oth;
    r0[3] = ob0.y * w_own + rb0.y * w_oth;
    r1[0] = oa1.x * w_own + ra1.x * w_oth;
    r1[1] = oa1.y * w_own + ra1.y * w_oth;
    r1[2] = ob1.x * w_own + rb1.x * w_oth;
    r1[3] = ob1.y * w_own + rb1.y * w_oth;
#pragma unroll
    for (int j = 0; j < 4; j++)
        res[j] = r0[j] + (r1[j] - r0[j]) * wy;

    // Lane q's channel group: q0->0-3, q1->8-11, q2->4-7, q3->12-15.
    int ch = (q & 1) * 8 + (q & 2) * 2;
#pragma unroll
    for (int j = 0; j < 4; j++)
        s_out[(ch + j) * SOUT_STRIDE + lp] = res[j];

    __syncthreads();

    // Writeback: thread i -> channel i>>4, float4 #(i&15). 256B contiguous
    // per channel plane, streaming stores.
    int c = tid >> 4;
    int v = tid & 15;
    float4 val = *reinterpret_cast<const float4*>(&s_out[c * SOUT_STRIDE + v * 4]);

    int pix_base = blockIdx.x * 64;
    int b  = pix_base / HW;
    int hw = pix_base - b * HW;         // multiple of 64
    float* o = out + ((size_t)b * CH + c) * HW + hw + v * 4;
    __stcs(reinterpret_cast<float4*>(o), val);
}

extern "C" void kernel_launch(void* const* d_in, const int* in_sizes, int n_in,
                              void* d_out, int out_size) {
    const float* x_grid = (const float*)d_in[0];
    const float* data   = (const float*)d_in[1];
    if (n_in >= 2 && in_sizes[0] == TT * CH) {
        data   = (const float*)d_in[0];
        x_grid = (const float*)d_in[1];
    }

    float* out = (float*)d_out;

    {
        int threads = 256;
        int blocks = (TT / 4 + threads - 1) / threads;  // 1024
        clamp_transpose_kernel<<<blocks, threads>>>(data);
    }
    {
        int blocks = NPIX / 64;                          // 36864, exact
        sample_kernel<<<blocks, 256>>>((const float2*)x_grid, out);
    }
}

// round 6
// speedup vs baseline: 1.1361x; 1.0281x over previous
#include <cuda_runtime.h>
#include <cuda_fp16.h>

#define TEXN   1024
#define TT     (TEXN * TEXN)
#define CH     16
#define BB     4
#define HH     768
#define WW     768
#define HW     (HH * WW)
#define NPIX   (BB * HW)

#define CLAMP_LO (-123.68f)
#define CLAMP_HI (151.061f)

// Channel-interleaved clamped texture, fp16 [y][x][c] (33.5 MB, L2-resident).
// +32 halves zero pad: 64B span load at x0==1023 overreads 32B; wx==0 there
// so the zero pad contributes 0 (no NaN).
__device__ __half g_tex[TT * CH + 32];

// ---------------------------------------------------------------------------
// Pass 1: clamp + transpose + fp16 convert, [C,T,T] f32 -> [T,T,C] f16.
// ---------------------------------------------------------------------------
__global__ __launch_bounds__(256)
void clamp_transpose_kernel(const float* __restrict__ data) {
    int p4 = (blockIdx.x * blockDim.x + threadIdx.x) * 4;
    if (p4 >= TT) return;

    __half h[4][CH];
#pragma unroll
    for (int c = 0; c < CH; c++) {
        float4 t = __ldcs(reinterpret_cast<const float4*>(&data[c * TT + p4]));
        h[0][c] = __float2half_rn(fminf(fmaxf(t.x, CLAMP_LO), CLAMP_HI));
        h[1][c] = __float2half_rn(fminf(fmaxf(t.y, CLAMP_LO), CLAMP_HI));
        h[2][c] = __float2half_rn(fminf(fmaxf(t.z, CLAMP_LO), CLAMP_HI));
        h[3][c] = __float2half_rn(fminf(fmaxf(t.w, CLAMP_LO), CLAMP_HI));
    }

    uint4* dst = reinterpret_cast<uint4*>(g_tex + (size_t)p4 * CH);
#pragma unroll
    for (int i = 0; i < 4; i++) {
        const uint4* src = reinterpret_cast<const uint4*>(&h[i][0]);
        dst[i * 2 + 0] = src[0];
        dst[i * 2 + 1] = src[1];
    }
}

// ---------------------------------------------------------------------------
// Pass 2: bilinear sample. 4 threads/pixel, 64 px/block (256 threads).
//   Loads: lane q takes the q-th 16B of the 64B (x0,x1) row span, rows y0,y1
//          (2 LDG.128/thread, ~2.5 L1 wf/px).
//   Exchange: 8B/row via 2 SHFL.32 — each lane gets the other x-corner for
//          its own 4 channels. Lane q owns ch {0-3,8-11,4-7,12-15}[q].
//   Math: x-lerp in half2 (HMUL2/HFMA2), y-lerp fp32.
//   Stores: smem [16ch][64px] stride 68, XOR-swizzled columns (conflict-free
//          STS and LDS.128 — verified bank maps), then 256B-contiguous
//          float4 __stcs per channel plane.
// ---------------------------------------------------------------------------
#define SOUT_STRIDE 68

__global__ __launch_bounds__(256)
void sample_kernel(const float2* __restrict__ grid, float* __restrict__ out) {
    __shared__ __align__(16) float s_out[CH * SOUT_STRIDE];

    int tid = threadIdx.x;
    int lp  = tid >> 2;                 // local pixel 0..63
    int q   = tid & 3;
    int pix = blockIdx.x * 64 + lp;     // exact grid: no guard

    float2 g = __ldg(&grid[pix]);

    // (g+1)*0.5*1023 = g*511.5 + 511.5, clipped to [0,1023]
    float ix = fminf(fmaxf(fmaf(g.x, 511.5f, 511.5f), 0.0f), 1023.0f);
    float iy = fminf(fmaxf(fmaf(g.y, 511.5f, 511.5f), 0.0f), 1023.0f);

    float x0f = floorf(ix);
    float y0f = floorf(iy);
    float wx = ix - x0f;
    float wy = iy - y0f;

    int x0 = (int)x0f;
    int y0 = (int)y0f;

    // u32 byte offsets: y*32768 + x*32 + q*16 (texture = 33.5MB < 4GB)
    unsigned row0 = ((unsigned)y0 << 15) + ((unsigned)x0 << 5) + ((unsigned)q << 4);
    unsigned row1 = row0 + ((y0 < TEXN - 1) ? 32768u : 0u);

    const char* tbase = reinterpret_cast<const char*>(g_tex);
    uint4 u0 = *reinterpret_cast<const uint4*>(tbase + row0);
    uint4 u1 = *reinterpret_cast<const uint4*>(tbase + row1);

    bool hiX = (q & 2) != 0;            // lanes 2,3 hold x1 data

    // Minimal exchange: send the 8B my partner needs, receive other-x for my
    // 4 channels. 2 SHFL per row.
    unsigned recv0a = __shfl_xor_sync(0xffffffffu, hiX ? u0.x : u0.z, 2);
    unsigned recv0b = __shfl_xor_sync(0xffffffffu, hiX ? u0.y : u0.w, 2);
    unsigned recv1a = __shfl_xor_sync(0xffffffffu, hiX ? u1.x : u1.z, 2);
    unsigned recv1b = __shfl_xor_sync(0xffffffffu, hiX ? u1.y : u1.w, 2);

    unsigned own0a = hiX ? u0.z : u0.x;
    unsigned own0b = hiX ? u0.w : u0.y;
    unsigned own1a = hiX ? u1.z : u1.x;
    unsigned own1b = hiX ? u1.w : u1.y;

    float w_own = hiX ? wx : (1.0f - wx);
    __half2 wo2 = __float2half2_rn(w_own);
    __half2 wt2 = __float2half2_rn(1.0f - w_own);

    // x-lerp in half2: r = own*w_own + recv*w_oth  (4 half2 results)
    __half2 r0a = __hfma2(*reinterpret_cast<__half2*>(&recv0a), wt2,
                  __hmul2(*reinterpret_cast<__half2*>(&own0a), wo2));
    __half2 r0b = __hfma2(*reinterpret_cast<__half2*>(&recv0b), wt2,
                  __hmul2(*reinterpret_cast<__half2*>(&own0b), wo2));
    __half2 r1a = __hfma2(*reinterpret_cast<__half2*>(&recv1a), wt2,
                  __hmul2(*reinterpret_cast<__half2*>(&own1a), wo2));
    __half2 r1b = __hfma2(*reinterpret_cast<__half2*>(&recv1b), wt2,
                  __hmul2(*reinterpret_cast<__half2*>(&own1b), wo2));

    // y-lerp in fp32
    float2 f0a = __half22float2(r0a);
    float2 f0b = __half22float2(r0b);
    float2 f1a = __half22float2(r1a);
    float2 f1b = __half22float2(r1b);

    float res[4];
    res[0] = f0a.x + (f1a.x - f0a.x) * wy;
    res[1] = f0a.y + (f1a.y - f0a.y) * wy;
    res[2] = f0b.x + (f1b.x - f0b.x) * wy;
    res[3] = f0b.y + (f1b.y - f0b.y) * wy;

    // Lane q's channel group: 0-3, 8-11, 4-7, 12-15. XOR-swizzled column
    // (k = q&1 == ch>=8 for the whole group) -> conflict-free STS.
    int ch  = (q & 1) * 8 + (q & 2) * 2;
    int col = lp ^ ((q & 1) << 3);
#pragma unroll
    for (int j = 0; j < 4; j++)
        s_out[(ch + j) * SOUT_STRIDE + col] = res[j];

    __syncthreads();

    // Writeback: thread i -> channel c=i>>4, float4 group v=i&15.
    // Un-swizzle: stored column for pixel p of channel c is p ^ (8*k(c)),
    // so float4 group index is v ^ (2*k(c)).
    int c  = tid >> 4;
    int v  = tid & 15;
    int vv = v ^ (((c >> 3) & 1) << 1);
    float4 val = *reinterpret_cast<const float4*>(&s_out[c * SOUT_STRIDE + vv * 4]);

    int pix_base = blockIdx.x * 64;
    int b  = pix_base / HW;
    int hw = pix_base - b * HW;         // multiple of 64
    float* o = out + ((size_t)b * CH + c) * HW + hw + v * 4;
    __stcs(reinterpret_cast<float4*>(o), val);
}

extern "C" void kernel_launch(void* const* d_in, const int* in_sizes, int n_in,
                              void* d_out, int out_size) {
    const float* x_grid = (const float*)d_in[0];
    const float* data   = (const float*)d_in[1];
    if (n_in >= 2 && in_sizes[0] == TT * CH) {
        data   = (const float*)d_in[0];
        x_grid = (const float*)d_in[1];
    }

    float* out = (float*)d_out;

    {
        int threads = 256;
        int blocks = (TT / 4 + threads - 1) / threads;  // 1024
        clamp_transpose_kernel<<<blocks, threads>>>(data);
    }
    {
        int blocks = NPIX / 64;                          // 36864, exact
        sample_kernel<<<blocks, 256>>>((const float2*)x_grid, out);
    }
}

// round 7
// speedup vs baseline: 1.2289x; 1.0817x over previous
#include <cuda_runtime.h>
#include <cuda_fp16.h>

#define TEXN   1024
#define TT     (TEXN * TEXN)
#define CH     16
#define BB     4
#define HH     768
#define WW     768
#define HW     (HH * WW)
#define NPIX   (BB * HW)

#define CLAMP_LO (-123.68f)
#define CLAMP_HI (151.061f)

// Channel-interleaved clamped texture, fp16 [y][x][c] (33.5 MB, L2-resident).
// +32 halves zero pad: 64B span load at x0==1023 overreads 32B; wx==0 there
// so the zero pad contributes 0*0 (no NaN).
__device__ __half g_tex[TT * CH + 32];

// ---------------------------------------------------------------------------
// Pass 1: clamp + transpose + fp16 convert, [C,T,T] f32 -> [T,T,C] f16.
// ---------------------------------------------------------------------------
__global__ __launch_bounds__(256)
void clamp_transpose_kernel(const float* __restrict__ data) {
    int p4 = (blockIdx.x * blockDim.x + threadIdx.x) * 4;
    if (p4 >= TT) return;

    __half h[4][CH];
#pragma unroll
    for (int c = 0; c < CH; c++) {
        float4 t = __ldcs(reinterpret_cast<const float4*>(&data[c * TT + p4]));
        h[0][c] = __float2half_rn(fminf(fmaxf(t.x, CLAMP_LO), CLAMP_HI));
        h[1][c] = __float2half_rn(fminf(fmaxf(t.y, CLAMP_LO), CLAMP_HI));
        h[2][c] = __float2half_rn(fminf(fmaxf(t.z, CLAMP_LO), CLAMP_HI));
        h[3][c] = __float2half_rn(fminf(fmaxf(t.w, CLAMP_LO), CLAMP_HI));
    }

    uint4* dst = reinterpret_cast<uint4*>(g_tex + (size_t)p4 * CH);
#pragma unroll
    for (int i = 0; i < 4; i++) {
        const uint4* src = reinterpret_cast<const uint4*>(&h[i][0]);
        dst[i * 2 + 0] = src[0];
        dst[i * 2 + 1] = src[1];
    }
}

// ---------------------------------------------------------------------------
// Pass 2: bilinear sample. 4 threads/pixel, 2 PIXELS PER THREAD,
// 128 px / block (256 threads). All 4 texture LDG.128 + 2 grid loads are
// issued before any dependent work -> MLP=4 hides the ~250cyc random-L2 hit.
//   Loads:   lane q takes the q-th 16B of the 64B (x0,x1) row span.
//   Exchange: 2 SHFL.32 per row -> other x-corner for my own 4 channels.
//   Math:    x-lerp half2, y-lerp fp32.
//   Stores:  smem [16][132], XOR-swizzled cols (verified conflict-free),
//            writeback 512B-contiguous float4 __stcs per channel plane.
// ---------------------------------------------------------------------------
#define SOUT_STRIDE 132   // 128 px + 4 pad floats; 528B row, 16B aligned

struct PixIn {
    uint4 u0, u1;       // raw 16B quarters, rows y0/y1
    float wx, wy;
};

__device__ __forceinline__ void compute_pix(const PixIn& p, bool hiX, float* res) {
    // minimal exchange: 8B per row
    unsigned recv0a = __shfl_xor_sync(0xffffffffu, hiX ? p.u0.x : p.u0.z, 2);
    unsigned recv0b = __shfl_xor_sync(0xffffffffu, hiX ? p.u0.y : p.u0.w, 2);
    unsigned recv1a = __shfl_xor_sync(0xffffffffu, hiX ? p.u1.x : p.u1.z, 2);
    unsigned recv1b = __shfl_xor_sync(0xffffffffu, hiX ? p.u1.y : p.u1.w, 2);

    unsigned own0a = hiX ? p.u0.z : p.u0.x;
    unsigned own0b = hiX ? p.u0.w : p.u0.y;
    unsigned own1a = hiX ? p.u1.z : p.u1.x;
    unsigned own1b = hiX ? p.u1.w : p.u1.y;

    float w_own = hiX ? p.wx : (1.0f - p.wx);
    __half2 wo2 = __float2half2_rn(w_own);
    __half2 wt2 = __float2half2_rn(1.0f - w_own);

    __half2 r0a = __hfma2(*reinterpret_cast<const __half2*>(&recv0a), wt2,
                  __hmul2(*reinterpret_cast<const __half2*>(&own0a), wo2));
    __half2 r0b = __hfma2(*reinterpret_cast<const __half2*>(&recv0b), wt2,
                  __hmul2(*reinterpret_cast<const __half2*>(&own0b), wo2));
    __half2 r1a = __hfma2(*reinterpret_cast<const __half2*>(&recv1a), wt2,
                  __hmul2(*reinterpret_cast<const __half2*>(&own1a), wo2));
    __half2 r1b = __hfma2(*reinterpret_cast<const __half2*>(&recv1b), wt2,
                  __hmul2(*reinterpret_cast<const __half2*>(&own1b), wo2));

    float2 f0a = __half22float2(r0a);
    float2 f0b = __half22float2(r0b);
    float2 f1a = __half22float2(r1a);
    float2 f1b = __half22float2(r1b);

    res[0] = f0a.x + (f1a.x - f0a.x) * p.wy;
    res[1] = f0a.y + (f1a.y - f0a.y) * p.wy;
    res[2] = f0b.x + (f1b.x - f0b.x) * p.wy;
    res[3] = f0b.y + (f1b.y - f0b.y) * p.wy;
}

__global__ __launch_bounds__(256)
void sample_kernel(const float2* __restrict__ grid, float* __restrict__ out) {
    __shared__ __align__(16) float s_out[CH * SOUT_STRIDE];

    int tid = threadIdx.x;
    int lp  = tid >> 2;                  // 0..63; handles px lp and lp+64
    int q   = tid & 3;
    int base = blockIdx.x * 128;         // exact grid; HW % 128 == 0

    // ---- issue all loads up front (MLP) ----
    float2 g0 = __ldg(&grid[base + lp]);
    float2 g1 = __ldg(&grid[base + lp + 64]);

    const char* tbase = reinterpret_cast<const char*>(g_tex);
    unsigned qoff = (unsigned)q << 4;

    PixIn p0, p1;
    {
        float ix = fminf(fmaxf(fmaf(g0.x, 511.5f, 511.5f), 0.0f), 1023.0f);
        float iy = fminf(fmaxf(fmaf(g0.y, 511.5f, 511.5f), 0.0f), 1023.0f);
        float x0f = floorf(ix), y0f = floorf(iy);
        p0.wx = ix - x0f; p0.wy = iy - y0f;
        int x0 = (int)x0f, y0 = (int)y0f;
        unsigned r0 = ((unsigned)y0 << 15) + ((unsigned)x0 << 5) + qoff;
        unsigned r1 = r0 + ((y0 < TEXN - 1) ? 32768u : 0u);
        p0.u0 = *reinterpret_cast<const uint4*>(tbase + r0);
        p0.u1 = *reinterpret_cast<const uint4*>(tbase + r1);
    }
    {
        float ix = fminf(fmaxf(fmaf(g1.x, 511.5f, 511.5f), 0.0f), 1023.0f);
        float iy = fminf(fmaxf(fmaf(g1.y, 511.5f, 511.5f), 0.0f), 1023.0f);
        float x0f = floorf(ix), y0f = floorf(iy);
        p1.wx = ix - x0f; p1.wy = iy - y0f;
        int x0 = (int)x0f, y0 = (int)y0f;
        unsigned r0 = ((unsigned)y0 << 15) + ((unsigned)x0 << 5) + qoff;
        unsigned r1 = r0 + ((y0 < TEXN - 1) ? 32768u : 0u);
        p1.u0 = *reinterpret_cast<const uint4*>(tbase + r0);
        p1.u1 = *reinterpret_cast<const uint4*>(tbase + r1);
    }

    bool hiX = (q & 2) != 0;
    float res0[4], res1[4];
    compute_pix(p0, hiX, res0);
    compute_pix(p1, hiX, res1);

    // lane q's channels: 0-3, 8-11, 4-7, 12-15; XOR-swizzled column
    int ch   = (q & 1) * 8 + (q & 2) * 2;
    int col0 = lp ^ ((q & 1) << 3);      // bit6 (the +64) untouched by XOR
#pragma unroll
    for (int j = 0; j < 4; j++) {
        s_out[(ch + j) * SOUT_STRIDE + col0]      = res0[j];
        s_out[(ch + j) * SOUT_STRIDE + col0 + 64] = res1[j];
    }

    __syncthreads();

    // Writeback: 2 rounds; round r, thread i -> channel (i+256r)>>5,
    // float4 group v=(i)&31. Un-swizzle group: v ^ 2*k(c).
    int b  = base / HW;
    int hw = base - b * HW;              // multiple of 128
#pragma unroll
    for (int r = 0; r < 2; r++) {
        int idx = tid + r * 256;
        int c = idx >> 5;                // 0..15, constant per warp
        int v = idx & 31;                // 0..31
        int vv = v ^ (((c >> 3) & 1) << 1);
        float4 val = *reinterpret_cast<const float4*>(&s_out[c * SOUT_STRIDE + vv * 4]);
        float* o = out + ((size_t)b * CH + c) * HW + hw + v * 4;
        __stcs(reinterpret_cast<float4*>(o), val);
    }
}

extern "C" void kernel_launch(void* const* d_in, const int* in_sizes, int n_in,
                              void* d_out, int out_size) {
    const float* x_grid = (const float*)d_in[0];
    const float* data   = (const float*)d_in[1];
    if (n_in >= 2 && in_sizes[0] == TT * CH) {
        data   = (const float*)d_in[0];
        x_grid = (const float*)d_in[1];
    }

    float* out = (float*)d_out;

    {
        int threads = 256;
        int blocks = (TT / 4 + threads - 1) / threads;  // 1024
        clamp_transpose_kernel<<<blocks, threads>>>(data);
    }
    {
        int blocks = NPIX / 128;                         // 18432, exact
        sample_kernel<<<blocks, 256>>>((const float2*)x_grid, out);
    }
}